// round 9
// baseline (speedup 1.0000x reference)
#include <cuda_runtime.h>
#include <cuda_bf16.h>
#include <math.h>
#include <stdint.h>

#define CB_K   1024
#define CH     128
#define QELEMS 8388608
#define NBLK   1024

__device__ float g_c2[CB_K];
__device__ int   g_maxc2bits = 0;
__device__ float g_partial[NBLK];
__device__ unsigned short g_cbbf[CB_K * 136];   // bf16 codebook, row stride 136 u16

// ---------------- helpers ----------------
__device__ __forceinline__ uint32_t smem_u32(const void* p) {
    uint32_t a;
    asm("{ .reg .u64 t; cvta.to.shared.u64 t, %1; cvt.u32.u64 %0, t; }" : "=r"(a) : "l"(p));
    return a;
}
__device__ __forceinline__ void cp_async16(uint32_t d, const void* s) {
    asm volatile("cp.async.cg.shared.global [%0], [%1], 16;" :: "r"(d), "l"(s));
}
#define CP_COMMIT() asm volatile("cp.async.commit_group;")
__device__ __forceinline__ uint32_t packbf(float lo, float hi) {
    uint32_t d;
    asm("cvt.rn.bf16x2.f32 %0, %1, %2;" : "=r"(d) : "f"(hi), "f"(lo));
    return d;
}
#define LDSM4(rr, addr)                                                          \
    asm volatile("ldmatrix.sync.aligned.m8n8.x4.shared.b16 {%0,%1,%2,%3}, [%4];" \
        : "=r"((rr)[0]),"=r"((rr)[1]),"=r"((rr)[2]),"=r"((rr)[3]) : "r"(addr))
#define MMA(dd, aa, b0, b1)                                                      \
    asm volatile("mma.sync.aligned.m16n8k16.row.col.f32.bf16.bf16.f32 "          \
        "{%0,%1,%2,%3}, {%4,%5,%6,%7}, {%8,%9}, {%0,%1,%2,%3};"                  \
        : "+f"((dd)[0]),"+f"((dd)[1]),"+f"((dd)[2]),"+f"((dd)[3])                \
        : "r"((aa)[0]),"r"((aa)[1]),"r"((aa)[2]),"r"((aa)[3]), "r"(b0),"r"(b1))

// ---------------------------------------------------------------------------
__global__ void prep_kernel(const float* __restrict__ codebook) {
    int k = blockIdx.x, c = threadIdx.x;
    float v = codebook[k * CH + c];
    __nv_bfloat16 hh = __float2bfloat16(v);
    g_cbbf[k * 136 + c] = *reinterpret_cast<unsigned short*>(&hh);
    float s = v * v;
    #pragma unroll
    for (int o = 16; o > 0; o >>= 1) s += __shfl_down_sync(0xffffffffu, s, o);
    __shared__ float ws[4];
    if ((c & 31) == 0) ws[c >> 5] = s;
    __syncthreads();
    if (c == 0) {
        float c2 = (ws[0] + ws[1]) + (ws[2] + ws[3]);
        g_c2[k] = c2;
        atomicMax(&g_maxc2bits, __float_as_int(c2));
    }
}

// ---------------------------------------------------------------------------
// SMEM word offsets (25728 words = 102.9KB -> 2 CTAs/SM)
// ---------------------------------------------------------------------------
#define W_ZST  0        // raw x fp32 [c][v] 128x64
#define W_CB   8192     // 3 B-buffers x 4352 words (buf2 = bf16 A image early)
#define W_AIMG 16896
#define W_C2   21248
#define W_NP   22272    // 16 slots x 64
#define W_RN2  23296
#define W_Z2   23360
#define W_RINV 23424
#define W_T    23488
#define W_PE   23552    // 16 x 64
#define W_PIX  24576    // 16 x 64
#define W_LS   25600
#define W_SIDX 25664
#define SMEM_WORDS 25728
#define SMEM_BYTES (SMEM_WORDS * 4)

__device__ __forceinline__ void issue_tile(uint32_t dstb, int j, int tid) {
    const unsigned char* src = reinterpret_cast<const unsigned char*>(g_cbbf)
                               + (size_t)j * 17408;
    #pragma unroll
    for (int it = 0; it < 5; ++it) {
        int idx = it * 256 + tid;
        if (idx < 1088) cp_async16(dstb + idx * 16, src + idx * 16);
    }
    CP_COMMIT();
}

__global__ void __launch_bounds__(256, 2)
vq_fused(const float* __restrict__ x, const float* __restrict__ codebook,
         float* __restrict__ out) {
    extern __shared__ uint32_t su[];
    float* sf = reinterpret_cast<float*>(su);
    int*   si = reinterpret_cast<int*>(su);
    const uint32_t sb = smem_u32(su);
    const int tid = threadIdx.x, w = tid >> 5, lane = tid & 31;
    const int rh = w & 1, cg = w >> 1;        // 32-row half / 16-code quarter
    const int n0 = blockIdx.x * 64;
    const int b = n0 >> 12, h = (n0 >> 6) & 63;

    issue_tile(sb + (W_CB + 0 * 4352) * 4, 0, tid);
    issue_tile(sb + (W_CB + 1 * 4352) * 4, 1, tid);

    // raw x tile -> zsT[c][v]
    const float* xbase = x + (size_t)b * (CH * 4096) + h * 64;
    {
        const int ww = tid & 63, c0 = tid >> 6;
        #pragma unroll
        for (int it = 0; it < 32; ++it) {
            int c = it * 4 + c0;
            sf[W_ZST + c * 64 + ww] = xbase[c * 4096 + ww];
        }
    }
    #pragma unroll
    for (int i = 0; i < 4; ++i) sf[W_C2 + i * 256 + tid] = g_c2[i * 256 + tid];
    __syncthreads();

    // norms: 4 threads per vector
    {
        int v = tid & 63, seg = tid >> 6;
        float s0 = 0.f, s1 = 0.f;
        #pragma unroll
        for (int i = 0; i < 16; ++i) {
            int c = seg * 32 + 2 * i;
            float a0 = sf[W_ZST + c * 64 + v], a1 = sf[W_ZST + (c + 1) * 64 + v];
            s0 = fmaf(a0, a0, s0); s1 = fmaf(a1, a1, s1);
        }
        sf[W_NP + seg * 64 + v] = s0 + s1;
    }
    __syncthreads();
    if (tid < 64) {
        float s = (sf[W_NP + tid] + sf[W_NP + 64 + tid])
                + (sf[W_NP + 128 + tid] + sf[W_NP + 192 + tid]);
        float r = 1.0f / fmaxf(sqrtf(s), 1e-12f);
        sf[W_RINV + tid] = r;
        sf[W_RN2  + tid] = 2.0f * r;
        sf[W_Z2   + tid] = s * r * r;
    }
    __syncthreads();

    // bf16 A image (normalized z) into buf2 region: 64 rows x 272B
    {
        int m = tid >> 2, qq = tid & 3;
        float r = sf[W_RINV + m];
        uint32_t* dst = su + W_AIMG + m * 68 + qq * 16;
        #pragma unroll
        for (int i = 0; i < 16; ++i) {
            int c = qq * 32 + 2 * i;
            dst[i] = packbf(sf[W_ZST + c * 64 + m] * r,
                            sf[W_ZST + (c + 1) * 64 + m] * r);
        }
    }
    __syncthreads();

    // A fragments: rows rh*32 .. +31 (2 m16 tiles), all K  (64 regs)
    uint32_t a[2][8][4];
    #pragma unroll
    for (int mt = 0; mt < 2; ++mt)
        #pragma unroll
        for (int kk = 0; kk < 8; ++kk) {
            uint32_t ad = sb + W_AIMG * 4 + (rh * 32 + mt * 16 + (lane & 15)) * 272
                        + (kk * 16 + (lane >> 4) * 8) * 2;
            LDSM4(a[mt][kk], ad);
        }
    __syncthreads();   // buf2 now free for B tiles

    const float wnd = sqrtf(__int_as_float(g_maxc2bits)) * 0.06f;
    const float OFF = 0.75f * __int_as_float(g_maxc2bits);
    const int rbase = rh * 32 + (lane >> 2);      // row(ri) = rbase + ri*8
    const int slot = cg * 4 + (lane & 3);

    float mn[4] = {3.4e38f, 3.4e38f, 3.4e38f, 3.4e38f};
    float be[4] = {3.4e38f, 3.4e38f, 3.4e38f, 3.4e38f};
    int   bi[4] = {0x7fffffff, 0x7fffffff, 0x7fffffff, 0x7fffffff};
    float Tr[4];

    for (int jj = 0; jj < 32; ++jj) {
        if (jj < 31) asm volatile("cp.async.wait_group 1;" ::: "memory");
        else         asm volatile("cp.async.wait_group 0;" ::: "memory");
        __syncthreads();
        if (jj + 2 < 32)
            issue_tile(sb + (W_CB + ((jj + 2) % 3) * 4352) * 4, (jj + 2) & 15, tid);

        if (jj == 16) {   // pass-1 -> per-vector threshold
            #pragma unroll
            for (int ri = 0; ri < 4; ++ri)
                sf[W_NP + slot * 64 + rbase + ri * 8] = mn[ri];
            __syncthreads();
            if (tid < 64) {
                float m = sf[W_NP + tid];
                #pragma unroll
                for (int qq = 1; qq < 16; ++qq) m = fminf(m, sf[W_NP + qq * 64 + tid]);
                sf[W_T + tid] = m + wnd;
            }
            __syncthreads();
            #pragma unroll
            for (int ri = 0; ri < 4; ++ri) Tr[ri] = sf[W_T + rbase + ri * 8];
        }

        const uint32_t cbb = sb + (W_CB + (jj % 3) * 4352) * 4;
        const int j = jj & 15;

        float d[2][2][4];
        #pragma unroll
        for (int mt = 0; mt < 2; ++mt)
            #pragma unroll
            for (int ng = 0; ng < 2; ++ng)
                #pragma unroll
                for (int i = 0; i < 4; ++i) d[mt][ng][i] = 0.f;

        #pragma unroll
        for (int kk = 0; kk < 8; ++kk) {
            uint32_t bfr[4];
            uint32_t ba = cbb + ((cg * 16 + (lane & 7) + ((lane >> 4) & 1) * 8) * 136
                        + kk * 16 + ((lane >> 3) & 1) * 8) * 2;
            LDSM4(bfr, ba);
            #pragma unroll
            for (int mt = 0; mt < 2; ++mt) {
                MMA(d[mt][0], a[mt][kk], bfr[0], bfr[1]);
                MMA(d[mt][1], a[mt][kk], bfr[2], bfr[3]);
            }
        }

        // epilogue: raw fp32 eoff = c2 - 2*dot - OFF (identical both passes)
        #pragma unroll
        for (int mt = 0; mt < 2; ++mt)
            #pragma unroll
            for (int ng = 0; ng < 2; ++ng) {
                int k0 = j * 64 + cg * 16 + ng * 8 + 2 * (lane & 3);
                float cv0 = sf[W_C2 + k0]     - OFF;
                float cv1 = sf[W_C2 + k0 + 1] - OFF;
                float e00 = fmaf(-2.f, d[mt][ng][0], cv0);
                float e01 = fmaf(-2.f, d[mt][ng][1], cv1);
                float e10 = fmaf(-2.f, d[mt][ng][2], cv0);
                float e11 = fmaf(-2.f, d[mt][ng][3], cv1);
                if (jj < 16) {
                    mn[mt * 2]     = fminf(mn[mt * 2],     fminf(e00, e01));
                    mn[mt * 2 + 1] = fminf(mn[mt * 2 + 1], fminf(e10, e11));
                } else {
                    #pragma unroll
                    for (int cand = 0; cand < 4; ++cand) {
                        float ev = (cand == 0) ? e00 : (cand == 1) ? e01
                                 : (cand == 2) ? e10 : e11;
                        int   ri = mt * 2 + (cand >> 1);
                        if (ev <= Tr[ri]) {
                            int row = rbase + ri * 8;
                            int k   = k0 + (cand & 1);
                            const float* cr = codebook + k * CH;
                            float d0 = 0.f, d1 = 0.f, d2 = 0.f, d3 = 0.f;
                            #pragma unroll
                            for (int c = 0; c < 128; c += 4) {
                                d0 = fmaf(sf[W_ZST + (c+0)*64 + row], cr[c+0], d0);
                                d1 = fmaf(sf[W_ZST + (c+1)*64 + row], cr[c+1], d1);
                                d2 = fmaf(sf[W_ZST + (c+2)*64 + row], cr[c+2], d2);
                                d3 = fmaf(sf[W_ZST + (c+3)*64 + row], cr[c+3], d3);
                            }
                            float ef = fmaf(-sf[W_RN2 + row], (d0 + d1) + (d2 + d3),
                                            sf[W_C2 + k]);
                            if (ef < be[ri]) { be[ri] = ef; bi[ri] = k; }
                        }
                    }
                }
            }
    }

    // ---- final per-vector reduce (16 slots/row, tie -> smallest index) ----
    #pragma unroll
    for (int ri = 0; ri < 4; ++ri) {
        sf[W_PE  + slot * 64 + rbase + ri * 8] = be[ri];
        si[W_PIX + slot * 64 + rbase + ri * 8] = bi[ri];
    }
    __syncthreads();
    if (tid < 64) {
        float bev = sf[W_PE + tid]; int biv = si[W_PIX + tid];
        #pragma unroll
        for (int qq = 1; qq < 16; ++qq) {
            float e2 = sf[W_PE + qq * 64 + tid];
            int   i2 = si[W_PIX + qq * 64 + tid];
            if (e2 < bev || (e2 == bev && i2 < biv)) { bev = e2; biv = i2; }
        }
        si[W_SIDX + tid] = biv;
        sf[W_LS + tid] = sqrtf(fmaxf(sf[W_Z2 + tid] + bev, 0.f));
    }
    __syncthreads();
    if (tid == 0) {
        float s = 0.f;
        #pragma unroll
        for (int i = 0; i < 64; ++i) s += sf[W_LS + i];
        g_partial[blockIdx.x] = s;
    }
    __syncthreads();

    // ---- q gather (coalesced codebook reads) + coalesced store ----
    float* qr = sf + W_CB;   // [64][129] = 8256 words
    {
        int wrp = tid >> 5, ln = tid & 31;
        #pragma unroll
        for (int vv = 0; vv < 8; ++vv) {
            int vx = wrp * 8 + vv;
            const float* cr = codebook + si[W_SIDX + vx] * CH;
            #pragma unroll
            for (int cc = 0; cc < 4; ++cc) {
                int c = cc * 32 + ln;
                qr[vx * 129 + c] = cr[c];
            }
        }
    }
    __syncthreads();
    {
        float* obase = out + (size_t)b * (CH * 4096) + h * 64;
        const int ww = tid & 63, c0 = tid >> 6;
        #pragma unroll
        for (int it = 0; it < 32; ++it) {
            int c = it * 4 + c0;
            obase[c * 4096 + ww] = qr[ww * 129 + c];
        }
    }
}

// ---------------------------------------------------------------------------
__global__ void finalize_kernel(float* __restrict__ out) {
    __shared__ float s[256];
    int t = threadIdx.x;
    float a = 0.f;
    #pragma unroll
    for (int i = 0; i < 4; ++i) a += g_partial[t + i * 256];
    s[t] = a;
    __syncthreads();
    for (int off = 128; off > 0; off >>= 1) {
        if (t < off) s[t] += s[t + off];
        __syncthreads();
    }
    if (t == 0) {
        float mean = s[0] * (1.0f / 65536.0f);
        out[QELEMS]     = 0.25f * mean;
        out[QELEMS + 1] = mean;
    }
}

extern "C" void kernel_launch(void* const* d_in, const int* in_sizes, int n_in,
                              void* d_out, int out_size) {
    const float* x        = (const float*)d_in[0];
    const float* codebook = (const float*)d_in[1];
    float*       out      = (float*)d_out;

    prep_kernel<<<CB_K, CH>>>(codebook);

    cudaFuncSetAttribute(vq_fused, cudaFuncAttributeMaxDynamicSharedMemorySize, SMEM_BYTES);
    vq_fused<<<NBLK, 256, SMEM_BYTES>>>(x, codebook, out);

    if (out_size >= QELEMS + 2)
        finalize_kernel<<<1, 256>>>(out);
}